// round 6
// baseline (speedup 1.0000x reference)
#include <cuda_runtime.h>

#define N_NODES 100000
#define N_EDGES 1600000
#define IN_CH   128
#define HEADS   4
#define OUT_CH  32
#define HC      128   // HEADS*OUT_CH

// ---------------- scratch (__device__ globals: no allocation allowed) ----------------
__device__ float g_xh[N_NODES * HC];          // 51.2 MB  node features after linear
__device__ float g_si[N_NODES * HEADS];       // per-node dot with att_i
__device__ float g_sj[N_NODES * HEADS];       // per-node dot with att_j
__device__ int   g_count[N_NODES];            // in-degree (by dst = row)
__device__ int   g_start[N_NODES];            // CSR exclusive offsets
__device__ int   g_cursor[N_NODES];           // scatter cursors
__device__ int   g_colsorted[N_EDGES];        // src node per sorted edge
__device__ float g_alpha[N_EDGES * HEADS];    // leaky-relu logits per sorted edge (float4)
__device__ float g_we[HEADS];                 // (lin_edge_w ⊙ att_e) row sums
__device__ int   g_stride;                    // 1 if edge_index stored int32, 2 if int64

#define SCAN_BLOCK 256
#define SCAN_ITEMS 8
#define SCAN_TILE  (SCAN_BLOCK * SCAN_ITEMS)
#define SCAN_NBLK  ((N_NODES + SCAN_TILE - 1) / SCAN_TILE)
__device__ int g_blocksums[SCAN_NBLK];

// ---------------- dtype probe: int64 edge_index has zero high words ----------------
// Values are node ids in [0, 100000): if stored as little-endian int64, every odd
// 32-bit word of the first 64 entries is 0. If int32, those words are uniform
// random ids — false-positive probability ~ (1e5/2^32)^64 ≈ 0.
__global__ void k_detect(const int* __restrict__ ei) {
    if (threadIdx.x == 0 && blockIdx.x == 0) {
        int allzero = 1;
        #pragma unroll 1
        for (int i = 0; i < 64; ++i)
            if (ei[2 * i + 1] != 0) { allzero = 0; break; }
        g_stride = allzero ? 2 : 1;   // 2: int64 viewed as int pairs; 1: int32
    }
}

// ---------------- init: zero histogram, fold edge-weight * att_e ----------------
__global__ void k_init(const float* __restrict__ lin_edge_w, const float* __restrict__ att) {
    int t = blockIdx.x * blockDim.x + threadIdx.x;
    if (t < N_NODES) g_count[t] = 0;
    if (t < HEADS) {
        float s = 0.f;
        #pragma unroll
        for (int c = 0; c < OUT_CH; ++c)
            s += lin_edge_w[t * OUT_CH + c] * att[t * 3 * OUT_CH + 2 * OUT_CH + c];
        g_we[t] = s;
    }
}

// ---------------- GEMM: xh[n][o] = sum_i x[n][i] * lin_w[o][i] ----------------
// 64-row x 128-col tile per block, 128 threads, 8x8 register micro-tile, K chunks of 32.
__global__ void k_gemm(const float* __restrict__ x, const float* __restrict__ w) {
    __shared__ __align__(16) float xs[32][68];   // xs[k][r], padded row
    __shared__ __align__(16) float ws[32][132];  // ws[k][c], padded row

    const int tid = threadIdx.x;            // 0..127
    const int tx  = tid & 15;               // col group 0..15  -> cols tx*8..tx*8+7
    const int ty  = tid >> 4;               // row group 0..7   -> rows ty*8..ty*8+7
    const int rowbase = blockIdx.x * 64;

    const float4* x4 = (const float4*)x;
    const float4* w4 = (const float4*)w;

    float acc[8][8];
    #pragma unroll
    for (int i = 0; i < 8; ++i)
        #pragma unroll
        for (int j = 0; j < 8; ++j) acc[i][j] = 0.f;

    for (int kc = 0; kc < IN_CH; kc += 32) {
        #pragma unroll
        for (int it = 0; it < 4; ++it) {
            int idx = tid + it * 128;           // 0..511
            int r = idx >> 3, q = idx & 7;      // q: float4 within 32-col chunk
            int grow = rowbase + r;
            float4 v = make_float4(0.f, 0.f, 0.f, 0.f);
            if (grow < N_NODES) v = x4[grow * (IN_CH / 4) + (kc >> 2) + q];
            xs[q * 4 + 0][r] = v.x; xs[q * 4 + 1][r] = v.y;
            xs[q * 4 + 2][r] = v.z; xs[q * 4 + 3][r] = v.w;
        }
        #pragma unroll
        for (int it = 0; it < 8; ++it) {
            int idx = tid + it * 128;           // 0..1023
            int c = idx >> 3, q = idx & 7;
            float4 v = w4[c * (IN_CH / 4) + (kc >> 2) + q];
            ws[q * 4 + 0][c] = v.x; ws[q * 4 + 1][c] = v.y;
            ws[q * 4 + 2][c] = v.z; ws[q * 4 + 3][c] = v.w;
        }
        __syncthreads();

        #pragma unroll
        for (int k = 0; k < 32; ++k) {
            float4 a0 = *(const float4*)&xs[k][ty * 8];
            float4 a1 = *(const float4*)&xs[k][ty * 8 + 4];
            float4 b0 = *(const float4*)&ws[k][tx * 8];
            float4 b1 = *(const float4*)&ws[k][tx * 8 + 4];
            float xr[8] = {a0.x, a0.y, a0.z, a0.w, a1.x, a1.y, a1.z, a1.w};
            float wc[8] = {b0.x, b0.y, b0.z, b0.w, b1.x, b1.y, b1.z, b1.w};
            #pragma unroll
            for (int i = 0; i < 8; ++i)
                #pragma unroll
                for (int j = 0; j < 8; ++j)
                    acc[i][j] = fmaf(xr[i], wc[j], acc[i][j]);
        }
        __syncthreads();
    }

    float4* xh4 = (float4*)g_xh;
    #pragma unroll
    for (int i = 0; i < 8; ++i) {
        int row = rowbase + ty * 8 + i;
        if (row < N_NODES) {
            float4 o0 = make_float4(acc[i][0], acc[i][1], acc[i][2], acc[i][3]);
            float4 o1 = make_float4(acc[i][4], acc[i][5], acc[i][6], acc[i][7]);
            xh4[row * (HC / 4) + tx * 2 + 0] = o0;
            xh4[row * (HC / 4) + tx * 2 + 1] = o1;
        }
    }
}

// ---------------- per-node attention dots: si/sj ----------------
__global__ void k_sisj(const float* __restrict__ att) {
    int gt = blockIdx.x * blockDim.x + threadIdx.x;
    int n = gt >> 5, lane = gt & 31;
    if (n >= N_NODES) return;
    int h = lane >> 3, ci = lane & 7;                 // head, float4 within head
    const float4* xh4  = (const float4*)g_xh;
    const float4* att4 = (const float4*)att;
    float4 v  = xh4[n * (HC / 4) + lane];
    float4 ai = att4[h * 24 + ci];                    // att_i
    float4 aj = att4[h * 24 + 8 + ci];                // att_j
    float si = v.x * ai.x + v.y * ai.y + v.z * ai.z + v.w * ai.w;
    float sj = v.x * aj.x + v.y * aj.y + v.z * aj.z + v.w * aj.w;
    #pragma unroll
    for (int o = 4; o >= 1; o >>= 1) {
        si += __shfl_xor_sync(0xffffffffu, si, o);
        sj += __shfl_xor_sync(0xffffffffu, sj, o);
    }
    if (ci == 0) {
        g_si[n * HEADS + h] = si;
        g_sj[n * HEADS + h] = sj;
    }
}

// ---------------- degree histogram (dst = row) ----------------
__global__ void k_degree(const int* __restrict__ ei32) {
    int e = blockIdx.x * blockDim.x + threadIdx.x;
    if (e >= N_EDGES) return;
    int st = g_stride;
    int r = ei32[st * e];
    if ((unsigned)r < N_NODES) atomicAdd(&g_count[r], 1);
}

// ---------------- 3-stage exclusive prefix sum over N counts ----------------
__global__ void k_scan1() {
    __shared__ int sh[SCAN_BLOCK];
    int base = blockIdx.x * SCAN_TILE + threadIdx.x * SCAN_ITEMS;
    int v[SCAN_ITEMS];
    int s = 0;
    #pragma unroll
    for (int i = 0; i < SCAN_ITEMS; ++i) {
        int idx = base + i;
        v[i] = (idx < N_NODES) ? g_count[idx] : 0;
        s += v[i];
    }
    sh[threadIdx.x] = s;
    __syncthreads();
    for (int off = 1; off < SCAN_BLOCK; off <<= 1) {
        int t = (threadIdx.x >= off) ? sh[threadIdx.x - off] : 0;
        __syncthreads();
        sh[threadIdx.x] += t;
        __syncthreads();
    }
    int excl = sh[threadIdx.x] - s;
    if (threadIdx.x == SCAN_BLOCK - 1) g_blocksums[blockIdx.x] = sh[SCAN_BLOCK - 1];
    int run = excl;
    #pragma unroll
    for (int i = 0; i < SCAN_ITEMS; ++i) {
        int idx = base + i;
        if (idx < N_NODES) g_start[idx] = run;
        run += v[i];
    }
}

__global__ void k_scan2() {
    if (threadIdx.x == 0 && blockIdx.x == 0) {
        int running = 0;
        for (int b = 0; b < SCAN_NBLK; ++b) {
            int t = g_blocksums[b];
            g_blocksums[b] = running;
            running += t;
        }
    }
}

__global__ void k_scan3() {
    int i = blockIdx.x * blockDim.x + threadIdx.x;
    if (i >= N_NODES) return;
    int st = g_start[i] + g_blocksums[i / SCAN_TILE];
    g_start[i]  = st;
    g_cursor[i] = st;
}

// ---------------- bucket scatter + attention logits ----------------
__global__ void k_scatter(const float* __restrict__ edge_attr, const int* __restrict__ ei32) {
    int e = blockIdx.x * blockDim.x + threadIdx.x;
    if (e >= N_EDGES) return;
    int st = g_stride;
    int r = ei32[st * e];
    int c = ei32[st * (N_EDGES + e)];
    if ((unsigned)r >= N_NODES || (unsigned)c >= N_NODES) return;
    float ea = edge_attr[e];
    int pos = atomicAdd(&g_cursor[r], 1);
    g_colsorted[pos] = c;
    float4 si = ((const float4*)g_si)[r];
    float4 sj = ((const float4*)g_sj)[c];
    float4 a;
    a.x = si.x + sj.x + ea * g_we[0];
    a.y = si.y + sj.y + ea * g_we[1];
    a.z = si.z + sj.z + ea * g_we[2];
    a.w = si.w + sj.w + ea * g_we[3];
    a.x = a.x > 0.f ? a.x : 0.2f * a.x;
    a.y = a.y > 0.f ? a.y : 0.2f * a.y;
    a.z = a.z > 0.f ? a.z : 0.2f * a.z;
    a.w = a.w > 0.f ? a.w : 0.2f * a.w;
    ((float4*)g_alpha)[pos] = a;
}

// ---------------- per-node softmax + weighted gather-aggregate (warp per node) ------
__global__ void k_aggregate(float* __restrict__ out) {
    int gt = blockIdx.x * blockDim.x + threadIdx.x;
    int n = gt >> 5, lane = gt & 31;
    if (n >= N_NODES) return;
    int s   = g_start[n];
    int deg = g_count[n];
    const float4* a4 = (const float4*)g_alpha;

    // pass 1: per-head max over incoming edges
    float4 m = make_float4(-1e30f, -1e30f, -1e30f, -1e30f);
    for (int j = lane; j < deg; j += 32) {
        float4 a = a4[s + j];
        m.x = fmaxf(m.x, a.x); m.y = fmaxf(m.y, a.y);
        m.z = fmaxf(m.z, a.z); m.w = fmaxf(m.w, a.w);
    }
    #pragma unroll
    for (int o = 16; o >= 1; o >>= 1) {
        m.x = fmaxf(m.x, __shfl_xor_sync(0xffffffffu, m.x, o));
        m.y = fmaxf(m.y, __shfl_xor_sync(0xffffffffu, m.y, o));
        m.z = fmaxf(m.z, __shfl_xor_sync(0xffffffffu, m.z, o));
        m.w = fmaxf(m.w, __shfl_xor_sync(0xffffffffu, m.w, o));
    }

    // pass 2: per-head sum of exp
    float4 sm = make_float4(0.f, 0.f, 0.f, 0.f);
    for (int j = lane; j < deg; j += 32) {
        float4 a = a4[s + j];
        sm.x += __expf(a.x - m.x); sm.y += __expf(a.y - m.y);
        sm.z += __expf(a.z - m.z); sm.w += __expf(a.w - m.w);
    }
    #pragma unroll
    for (int o = 16; o >= 1; o >>= 1) {
        sm.x += __shfl_xor_sync(0xffffffffu, sm.x, o);
        sm.y += __shfl_xor_sync(0xffffffffu, sm.y, o);
        sm.z += __shfl_xor_sync(0xffffffffu, sm.z, o);
        sm.w += __shfl_xor_sync(0xffffffffu, sm.w, o);
    }
    float4 inv;
    inv.x = 1.f / (sm.x + 1e-16f); inv.y = 1.f / (sm.y + 1e-16f);
    inv.z = 1.f / (sm.z + 1e-16f); inv.w = 1.f / (sm.w + 1e-16f);

    int h = lane >> 3;
    float mh   = (h < 2) ? (h == 0 ? m.x : m.y)   : (h == 2 ? m.z : m.w);
    float invh = (h < 2) ? (h == 0 ? inv.x : inv.y) : (h == 2 ? inv.z : inv.w);

    // pass 3: gather xh[col] (512B per warp-edge, L2-resident) and accumulate
    float4 acc = make_float4(0.f, 0.f, 0.f, 0.f);
    const float4* xh4 = (const float4*)g_xh;
    const int*   cs   = g_colsorted + s;
    const float* al   = g_alpha + (size_t)s * HEADS + h;
    #pragma unroll 2
    for (int j = 0; j < deg; ++j) {
        int c   = __ldg(cs + j);                       // warp-uniform broadcast load
        float a = __ldg(al + j * HEADS);               // 4 distinct floats per 16B line
        float w = __expf(a - mh) * invh;
        float4 v = xh4[c * (HC / 4) + lane];
        acc.x = fmaf(w, v.x, acc.x);
        acc.y = fmaf(w, v.y, acc.y);
        acc.z = fmaf(w, v.z, acc.z);
        acc.w = fmaf(w, v.w, acc.w);
    }
    ((float4*)out)[n * (HC / 4) + lane] = acc;
}

// ---------------- launch ----------------
extern "C" void kernel_launch(void* const* d_in, const int* in_sizes, int n_in,
                              void* d_out, int out_size) {
    const float* x           = (const float*)d_in[0];
    const float* edge_attr   = (const float*)d_in[1];
    const int*   ei32        = (const int*)d_in[2];   // int32 or int64 — probed at runtime
    const float* lin_w       = (const float*)d_in[3];
    const float* lin_edge_w  = (const float*)d_in[4];
    const float* att         = (const float*)d_in[5];
    float* out = (float*)d_out;

    k_detect <<<1, 32>>>(ei32);
    k_init   <<<(N_NODES + 255) / 256, 256>>>(lin_edge_w, att);
    k_gemm   <<<(N_NODES + 63) / 64, 128>>>(x, lin_w);
    k_sisj   <<<(N_NODES * 32 + 255) / 256, 256>>>(att);
    k_degree <<<(N_EDGES + 255) / 256, 256>>>(ei32);
    k_scan1  <<<SCAN_NBLK, SCAN_BLOCK>>>();
    k_scan2  <<<1, 32>>>();
    k_scan3  <<<(N_NODES + 255) / 256, 256>>>();
    k_scatter<<<(N_EDGES + 255) / 256, 256>>>(edge_attr, ei32);
    k_aggregate<<<(N_NODES * 32 + 255) / 256, 256>>>(out);
}